// round 1
// baseline (speedup 1.0000x reference)
#include <cuda_runtime.h>
#include <cstdint>
#include <cstdio>

#define D_MODEL 768
#define HEADS   12
#define DK      64
#define SEQ     2048
#define BATCH   2
#define MTOK    (BATCH*SEQ)   // 4096 token rows
#define DFF     3072
#define LN_EPS  1e-6f

// ---------------- scratch (device globals: allocation-free) ----------------
__device__ float g_q   [MTOK*D_MODEL];
__device__ float g_k   [MTOK*D_MODEL];
__device__ float g_v   [MTOK*D_MODEL];
__device__ float g_attn[MTOK*D_MODEL];
__device__ float g_tmp [MTOK*D_MODEL];
__device__ float g_x1  [MTOK*D_MODEL];
__device__ float g_ff1 [MTOK*DFF];
__device__ int   g_mask_mode;   // 0 = 4-byte elements (int32/float), 1 = 1-byte elements

// ---------------- mask dtype detection ----------------
// int32/float32 masks have every word in {0,1,0x3F800000}; a byte-packed bool
// buffer read as words essentially never does (prob ~ (2/16)^128).
__global__ void detect_mask_kernel(const unsigned int* __restrict__ m)
{
    unsigned ok = 1u;
    for (int i = 0; i < 128; i++) {
        unsigned w = m[i];
        if (w != 0u && w != 1u && w != 0x3F800000u) { ok = 0u; break; }
    }
    g_mask_mode = ok ? 0 : 1;
}

// ---------------- SGEMM: C[M,N] = A[M,K] * B[N,K]^T + bias[N] (opt ReLU) ----------------
// 128x128 tile, BK=16, 256 threads, 8x8 microtile.
template<int RELU>
__global__ __launch_bounds__(256, 2)
void sgemm_abt(const float* __restrict__ A, const float* __restrict__ B,
               const float* __restrict__ bias, float* __restrict__ C,
               int M, int N, int K)
{
    __shared__ float As[16][128];
    __shared__ float Bs[16][128];

    const int tid = threadIdx.x;
    const int tx = tid & 15;          // n microtile
    const int ty = tid >> 4;          // m microtile
    const int m0 = blockIdx.y * 128;
    const int n0 = blockIdx.x * 128;

    float acc[8][8];
    #pragma unroll
    for (int i = 0; i < 8; i++)
        #pragma unroll
        for (int j = 0; j < 8; j++) acc[i][j] = 0.f;

    for (int k0 = 0; k0 < K; k0 += 16) {
        // cooperative load: 128x16 of A and B, stored transposed [k][row]
        #pragma unroll
        for (int L = 0; L < 2; L++) {
            int f  = L * 256 + tid;       // 0..511 float4 slots
            int r  = f >> 2;              // row 0..127
            int kc = (f & 3) << 2;        // 0,4,8,12
            float4 av = *(const float4*)(A + (size_t)(m0 + r) * K + k0 + kc);
            As[kc+0][r] = av.x; As[kc+1][r] = av.y; As[kc+2][r] = av.z; As[kc+3][r] = av.w;
            float4 bv = *(const float4*)(B + (size_t)(n0 + r) * K + k0 + kc);
            Bs[kc+0][r] = bv.x; Bs[kc+1][r] = bv.y; Bs[kc+2][r] = bv.z; Bs[kc+3][r] = bv.w;
        }
        __syncthreads();

        #pragma unroll
        for (int kk = 0; kk < 16; kk++) {
            float a[8], b[8];
            *(float4*)&a[0] = *(const float4*)&As[kk][ty * 8 + 0];
            *(float4*)&a[4] = *(const float4*)&As[kk][ty * 8 + 4];
            *(float4*)&b[0] = *(const float4*)&Bs[kk][tx * 8 + 0];
            *(float4*)&b[4] = *(const float4*)&Bs[kk][tx * 8 + 4];
            #pragma unroll
            for (int i = 0; i < 8; i++)
                #pragma unroll
                for (int j = 0; j < 8; j++)
                    acc[i][j] = fmaf(a[i], b[j], acc[i][j]);
        }
        __syncthreads();
    }

    float bv[8];
    #pragma unroll
    for (int j = 0; j < 8; j++) bv[j] = bias[n0 + tx * 8 + j];

    #pragma unroll
    for (int i = 0; i < 8; i++) {
        float* cp = C + (size_t)(m0 + ty * 8 + i) * N + n0 + tx * 8;
        float outv[8];
        #pragma unroll
        for (int j = 0; j < 8; j++) {
            float v = acc[i][j] + bv[j];
            if (RELU) v = fmaxf(v, 0.f);
            outv[j] = v;
        }
        *(float4*)(cp + 0) = *(float4*)&outv[0];
        *(float4*)(cp + 4) = *(float4*)&outv[4];
    }
}

// ---------------- attention: flash-style, one query per thread ----------------
// grid (SEQ/128, HEADS, BATCH), 128 threads. Q,K,V are [B*S, D_MODEL] with the
// head slice at column h*DK. Output written in [B,S,D] layout directly.
__global__ __launch_bounds__(128)
void attention_kernel(const float* __restrict__ Q, const float* __restrict__ K,
                      const float* __restrict__ V, const void* __restrict__ mask,
                      float* __restrict__ O)
{
    __shared__ float Ks[32][DK];     // 8 KB
    __shared__ float Vs[32][DK];     // 8 KB
    __shared__ float Sb[32][128];    // 16 KB  (scores, [key][thread])
    __shared__ float Mk[32];

    const int tid  = threadIdx.x;
    const int h    = blockIdx.y;
    const int b    = blockIdx.z;
    const int qrow = blockIdx.x * 128 + tid;

    const float* qptr = Q + ((size_t)(b * SEQ + qrow)) * D_MODEL + h * DK;
    float q[DK], o[DK];
    #pragma unroll
    for (int d = 0; d < DK; d++) { q[d] = qptr[d]; o[d] = 0.f; }

    float m = -1e30f, l = 0.f;
    const int mode = g_mask_mode;

    for (int kt = 0; kt < SEQ / 32; kt++) {
        // load 32x64 K and V tiles (512 float4 each / 128 threads = 4 each)
        #pragma unroll
        for (int it = 0; it < 4; it++) {
            int f = it * 128 + tid;        // 0..511
            int r = f >> 4;                // key row in tile
            int c = (f & 15) << 2;         // col (float4)
            size_t base = ((size_t)(b * SEQ + kt * 32 + r)) * D_MODEL + h * DK + c;
            *(float4*)&Ks[r][c] = *(const float4*)(K + base);
            *(float4*)&Vs[r][c] = *(const float4*)(V + base);
        }
        if (tid < 32) {
            int bi = b * SEQ + kt * 32 + tid;
            int mv = (mode == 0) ? (((const unsigned int*)mask)[bi] != 0u)
                                 : (((const unsigned char*)mask)[bi] != 0);
            Mk[tid] = mv ? 1.f : 0.f;
        }
        __syncthreads();

        // pass 1: scores + tile max (K reads are warp-uniform -> broadcast)
        float tmax = -1e30f;
        #pragma unroll 2
        for (int j = 0; j < 32; j++) {
            float s = 0.f;
            #pragma unroll
            for (int d = 0; d < DK; d++) s = fmaf(q[d], Ks[j][d], s);
            s = (Mk[j] != 0.f) ? -1e9f : s * 0.125f;   // exact torch/jax masking
            Sb[j][tid] = s;
            tmax = fmaxf(tmax, s);
        }

        float mnew = fmaxf(m, tmax);
        float corr = __expf(m - mnew);
        l *= corr;
        #pragma unroll
        for (int d = 0; d < DK; d++) o[d] *= corr;

        // pass 2: exp + PV accumulate
        #pragma unroll 2
        for (int j = 0; j < 32; j++) {
            float p = __expf(Sb[j][tid] - mnew);
            l += p;
            #pragma unroll
            for (int d = 0; d < DK; d++) o[d] = fmaf(p, Vs[j][d], o[d]);
        }
        m = mnew;
        __syncthreads();
    }

    float inv = 1.f / l;
    float* op = O + ((size_t)(b * SEQ + qrow)) * D_MODEL + h * DK;
    #pragma unroll
    for (int d = 0; d < DK; d++) op[d] = o[d] * inv;
}

// ---------------- residual + LayerNorm (torch: ddof=1, /(std+eps)) ----------------
__global__ __launch_bounds__(256)
void ln_kernel(const float* __restrict__ X, const float* __restrict__ R,
               const float* __restrict__ gamma, const float* __restrict__ beta,
               float* __restrict__ Y)
{
    const int row = blockIdx.x;
    const int tid = threadIdx.x;
    __shared__ float red1[8], red2[8];

    float v[3];
    float s = 0.f, ss = 0.f;
    #pragma unroll
    for (int i = 0; i < 3; i++) {
        int c = i * 256 + tid;
        float a = X[(size_t)row * D_MODEL + c] + R[(size_t)row * D_MODEL + c];
        v[i] = a; s += a; ss += a * a;
    }
    #pragma unroll
    for (int off = 16; off > 0; off >>= 1) {
        s  += __shfl_xor_sync(0xffffffffu, s,  off);
        ss += __shfl_xor_sync(0xffffffffu, ss, off);
    }
    const int wid = tid >> 5, lid = tid & 31;
    if (lid == 0) { red1[wid] = s; red2[wid] = ss; }
    __syncthreads();
    float ts = 0.f, tss = 0.f;
    #pragma unroll
    for (int i = 0; i < 8; i++) { ts += red1[i]; tss += red2[i]; }

    float mean = ts * (1.f / 768.f);
    float var  = (tss - 768.f * mean * mean) * (1.f / 767.f);
    var = fmaxf(var, 0.f);
    float denom = 1.f / (sqrtf(var) + LN_EPS);

    #pragma unroll
    for (int i = 0; i < 3; i++) {
        int c = i * 256 + tid;
        Y[(size_t)row * D_MODEL + c] = gamma[c] * (v[i] - mean) * denom + beta[c];
    }
}

// ---------------- launcher ----------------
extern "C" void kernel_launch(void* const* d_in, const int* in_sizes, int n_in,
                              void* d_out, int out_size)
{
    const float* x   = (const float*)d_in[0];
    const void*  mask=               d_in[1];
    const float* wq  = (const float*)d_in[2];
    const float* bq  = (const float*)d_in[3];
    const float* wk  = (const float*)d_in[4];
    const float* bk  = (const float*)d_in[5];
    const float* wv  = (const float*)d_in[6];
    const float* bv  = (const float*)d_in[7];
    const float* wo  = (const float*)d_in[8];
    const float* bo  = (const float*)d_in[9];
    const float* w1  = (const float*)d_in[10];
    const float* b1  = (const float*)d_in[11];
    const float* w2  = (const float*)d_in[12];
    const float* b2  = (const float*)d_in[13];
    const float* g1  = (const float*)d_in[14];
    const float* be1 = (const float*)d_in[15];
    const float* g2  = (const float*)d_in[16];
    const float* be2 = (const float*)d_in[17];
    float* out = (float*)d_out;

    // resolve scratch pointers once (first call is the non-captured
    // correctness run; the capture call then performs zero runtime-API calls)
    static float *qb=nullptr,*kb=nullptr,*vb=nullptr,*attn=nullptr,*tmp=nullptr,*x1=nullptr,*ff1=nullptr;
    if (!qb) {
        cudaGetSymbolAddress((void**)&qb,   g_q);
        cudaGetSymbolAddress((void**)&kb,   g_k);
        cudaGetSymbolAddress((void**)&vb,   g_v);
        cudaGetSymbolAddress((void**)&attn, g_attn);
        cudaGetSymbolAddress((void**)&tmp,  g_tmp);
        cudaGetSymbolAddress((void**)&x1,   g_x1);
        cudaGetSymbolAddress((void**)&ff1,  g_ff1);
    }

    detect_mask_kernel<<<1, 1>>>((const unsigned int*)mask);

    dim3 g768(D_MODEL / 128, MTOK / 128);            // (6, 32)
    sgemm_abt<0><<<g768, 256>>>(x, wq, bq, qb, MTOK, D_MODEL, D_MODEL);
    sgemm_abt<0><<<g768, 256>>>(x, wk, bk, kb, MTOK, D_MODEL, D_MODEL);
    sgemm_abt<0><<<g768, 256>>>(x, wv, bv, vb, MTOK, D_MODEL, D_MODEL);

    attention_kernel<<<dim3(SEQ / 128, HEADS, BATCH), 128>>>(qb, kb, vb, mask, attn);

    sgemm_abt<0><<<g768, 256>>>(attn, wo, bo, tmp, MTOK, D_MODEL, D_MODEL);
    ln_kernel<<<MTOK, 256>>>(x, tmp, g1, be1, x1);

    sgemm_abt<1><<<dim3(DFF / 128, MTOK / 128), 256>>>(x1, w1, b1, ff1, MTOK, DFF, D_MODEL);
    sgemm_abt<0><<<g768, 256>>>(ff1, w2, b2, tmp, MTOK, D_MODEL, DFF);
    ln_kernel<<<MTOK, 256>>>(x1, tmp, g2, be2, out);
}

// round 7
// speedup vs baseline: 1.6041x; 1.6041x over previous
#include <cuda_runtime.h>
#include <cstdint>
#include <cstdio>

#define D_MODEL 768
#define HEADS   12
#define DK      64
#define SEQ     2048
#define BATCH   2
#define MTOK    (BATCH*SEQ)   // 4096 token rows
#define DFF     3072
#define LN_EPS  1e-6f

// ---------------- helpers ----------------
__device__ __forceinline__ uint32_t smem_u32(const void* p) {
    uint32_t a;
    asm("{ .reg .u64 t; cvta.to.shared.u64 t, %1; cvt.u32.u64 %0, t; }" : "=r"(a) : "l"(p));
    return a;
}

__device__ __forceinline__ void ldmx4(uint32_t* f, uint32_t addr) {
    asm volatile("ldmatrix.sync.aligned.m8n8.x4.shared.b16 {%0,%1,%2,%3}, [%4];"
                 : "=r"(f[0]), "=r"(f[1]), "=r"(f[2]), "=r"(f[3]) : "r"(addr));
}

__device__ __forceinline__ void mma16816(float* d, const uint32_t* a, uint32_t b0, uint32_t b1) {
    asm volatile("mma.sync.aligned.m16n8k16.row.col.f32.bf16.bf16.f32 "
                 "{%0,%1,%2,%3}, {%4,%5,%6,%7}, {%8,%9}, {%0,%1,%2,%3};"
                 : "+f"(d[0]), "+f"(d[1]), "+f"(d[2]), "+f"(d[3])
                 : "r"(a[0]), "r"(a[1]), "r"(a[2]), "r"(a[3]), "r"(b0), "r"(b1));
}

// split 2 fp32 -> packed bf16 hi word + lo word (lo = a - bf16(a))
__device__ __forceinline__ void split2(float a0, float a1, uint32_t& hw, uint32_t& lw) {
    asm("cvt.rn.bf16x2.f32 %0, %1, %2;" : "=r"(hw) : "f"(a1), "f"(a0));
    float h0 = __uint_as_float(hw << 16);
    float h1 = __uint_as_float(hw & 0xffff0000u);
    float l0 = a0 - h0;
    float l1 = a1 - h1;
    asm("cvt.rn.bf16x2.f32 %0, %1, %2;" : "=r"(lw) : "f"(l1), "f"(l0));
}

// ---------------- scratch (device globals: allocation-free) ----------------
__device__ float g_q   [MTOK*D_MODEL];
__device__ float g_k   [MTOK*D_MODEL];
__device__ float g_v   [MTOK*D_MODEL];
__device__ float g_attn[MTOK*D_MODEL];
__device__ float g_tmp [MTOK*D_MODEL];
__device__ float g_x1  [MTOK*D_MODEL];
__device__ float g_ff1 [MTOK*DFF];
__device__ int   g_mask_mode;   // 0 = 4-byte elements, 1 = 1-byte elements

// ---------------- mask dtype detection ----------------
__global__ void detect_mask_kernel(const unsigned int* __restrict__ m)
{
    unsigned ok = 1u;
    for (int i = 0; i < 128; i++) {
        unsigned w = m[i];
        if (w != 0u && w != 1u && w != 0x3F800000u) { ok = 0u; break; }
    }
    g_mask_mode = ok ? 0 : 1;
}

// ================= HMMA GEMM (mma.sync bf16, 3-term split) =================
// C[M,N] = A[M,K] * B[N,K]^T + bias[N] (opt ReLU), fp32 in/out.
// CTA 128x128, 8 warps of 64x32, K-chunk 16, double-buffered SMEM.
// SMEM per buffer: Ahi/Alo/Bhi/Blo, each 128 rows x 48B (16 bf16 + pad) = 6KB.
#define MAT_BYTES 6144          // 128*48
#define BUF_BYTES (4*MAT_BYTES) // 24KB
#define STRIDE    48

template<int RELU>
__global__ __launch_bounds__(256, 1)
void gemm_mma(const float* __restrict__ A, const float* __restrict__ B,
              const float* __restrict__ bias, float* __restrict__ C,
              int M, int N, int K)
{
    __shared__ __align__(16) unsigned char sm[2 * BUF_BYTES];   // 48KB

    const int tid  = threadIdx.x;
    const int lane = tid & 31;
    const int wid  = tid >> 5;
    const int m0 = blockIdx.y * 128;
    const int n0 = blockIdx.x * 128;
    const int wm = (wid & 1) * 64;     // warp row offset in tile
    const int wn = (wid >> 1) * 32;    // warp col offset in tile
    const uint32_t sbase = smem_u32(sm);

    float acc[4][4][4];
    #pragma unroll
    for (int i = 0; i < 4; i++)
        #pragma unroll
        for (int j = 0; j < 4; j++)
            #pragma unroll
            for (int k = 0; k < 4; k++) acc[i][j][k] = 0.f;

    // LDG slot mapping: slot s -> row s>>2, float4-col (s&3)*4 ; thread owns s=tid, tid+256
    const int r1  = tid >> 2;            // 0..63
    const int c4a = (tid & 3) << 2;      // 0,4,8,12

    const float* Ap = A + (size_t)m0 * K;
    const float* Bp = B + (size_t)n0 * K;

    float4 ra0, ra1, rb0, rb1;
    ra0 = *(const float4*)(Ap + (size_t)r1 * K + c4a);
    ra1 = *(const float4*)(Ap + (size_t)(r1 + 64) * K + c4a);
    rb0 = *(const float4*)(Bp + (size_t)r1 * K + c4a);
    rb1 = *(const float4*)(Bp + (size_t)(r1 + 64) * K + c4a);

    // per-warp ldmatrix address components (within a buffer)
    const int  arow0 = wm + (lane & 15);
    const uint32_t acolb = (uint32_t)((lane >> 4) << 4);
    const int  g     = lane >> 3;
    const int  brow0 = wn + ((g >> 1) << 3) + (lane & 7);
    const uint32_t bcolb = (uint32_t)((g & 1) << 4);

    const int NC = K >> 4;
    for (int c = 0; c < NC; c++) {
        const uint32_t bufb = sbase + (uint32_t)(c & 1) * BUF_BYTES;
        unsigned char* bufp = sm + (c & 1) * BUF_BYTES;

        // ---- STS: split fp32 -> bf16 hi/lo and store padded rows ----
        {
            uint32_t h, l, h2, l2;
            uint32_t o1 = (uint32_t)(r1 * STRIDE + (c4a << 1));
            uint32_t o2 = (uint32_t)((r1 + 64) * STRIDE + (c4a << 1));

            split2(ra0.x, ra0.y, h, l); split2(ra0.z, ra0.w, h2, l2);
            *(uint32_t*)(bufp + o1)                 = h;
            *(uint32_t*)(bufp + o1 + 4)             = h2;
            *(uint32_t*)(bufp + MAT_BYTES + o1)     = l;
            *(uint32_t*)(bufp + MAT_BYTES + o1 + 4) = l2;

            split2(ra1.x, ra1.y, h, l); split2(ra1.z, ra1.w, h2, l2);
            *(uint32_t*)(bufp + o2)                 = h;
            *(uint32_t*)(bufp + o2 + 4)             = h2;
            *(uint32_t*)(bufp + MAT_BYTES + o2)     = l;
            *(uint32_t*)(bufp + MAT_BYTES + o2 + 4) = l2;

            split2(rb0.x, rb0.y, h, l); split2(rb0.z, rb0.w, h2, l2);
            *(uint32_t*)(bufp + 2*MAT_BYTES + o1)     = h;
            *(uint32_t*)(bufp + 2*MAT_BYTES + o1 + 4) = h2;
            *(uint32_t*)(bufp + 3*MAT_BYTES + o1)     = l;
            *(uint32_t*)(bufp + 3*MAT_BYTES + o1 + 4) = l2;

            split2(rb1.x, rb1.y, h, l); split2(rb1.z, rb1.w, h2, l2);
            *(uint32_t*)(bufp + 2*MAT_BYTES + o2)     = h;
            *(uint32_t*)(bufp + 2*MAT_BYTES + o2 + 4) = h2;
            *(uint32_t*)(bufp + 3*MAT_BYTES + o2)     = l;
            *(uint32_t*)(bufp + 3*MAT_BYTES + o2 + 4) = l2;
        }

        // ---- prefetch next chunk (overlaps the barrier + lds/mma below) ----
        if (c + 1 < NC) {
            const float* An = Ap + (size_t)(c + 1) * 16;
            const float* Bn = Bp + (size_t)(c + 1) * 16;
            ra0 = *(const float4*)(An + (size_t)r1 * K + c4a);
            ra1 = *(const float4*)(An + (size_t)(r1 + 64) * K + c4a);
            rb0 = *(const float4*)(Bn + (size_t)r1 * K + c4a);
            rb1 = *(const float4*)(Bn + (size_t)(r1 + 64) * K + c4a);
        }

        __syncthreads();

        // ---- ldmatrix fragments ----
        uint32_t Ah[4][4], Al[4][4], Bh[2][4], Bl[2][4];
        #pragma unroll
        for (int mi = 0; mi < 4; mi++) {
            uint32_t ao = bufb + (uint32_t)((arow0 + mi * 16) * STRIDE) + acolb;
            ldmx4(Ah[mi], ao);
            ldmx4(Al[mi], ao + MAT_BYTES);
        }
        {
            uint32_t bo = bufb + 2*MAT_BYTES + (uint32_t)(brow0 * STRIDE) + bcolb;
            ldmx4(Bh[0], bo);
            ldmx4(Bh[1], bo + 16 * STRIDE);
            ldmx4(Bl[0], bo + MAT_BYTES);
            ldmx4(Bl[1], bo + MAT_BYTES + 16 * STRIDE);
        }

        // ---- 48 MMAs: AhiBhi + AhiBlo + AloBhi ----
        #pragma unroll
        for (int mi = 0; mi < 4; mi++) {
            #pragma unroll
            for (int ni = 0; ni < 4; ni++) {
                uint32_t bh0 = Bh[ni >> 1][(ni & 1) * 2];
                uint32_t bh1 = Bh[ni >> 1][(ni & 1) * 2 + 1];
                uint32_t bl0 = Bl[ni >> 1][(ni & 1) * 2];
                uint32_t bl1 = Bl[ni >> 1][(ni & 1) * 2 + 1];
                mma16816(acc[mi][ni], Ah[mi], bh0, bh1);
                mma16816(acc[mi][ni], Ah[mi], bl0, bl1);
                mma16816(acc[mi][ni], Al[mi], bh0, bh1);
            }
        }
        // no trailing sync needed: this iter's lds reads complete before this
        // thread's next-iter sts, and cross-thread reuse of this buffer is
        // fenced by the NEXT iteration's __syncthreads (double buffering).
    }

    // ---- epilogue ----
    #pragma unroll
    for (int mi = 0; mi < 4; mi++) {
        int r = m0 + wm + mi * 16 + (lane >> 2);
        #pragma unroll
        for (int ni = 0; ni < 4; ni++) {
            int col = n0 + wn + ni * 8 + (lane & 3) * 2;
            float b0 = bias[col], b1 = bias[col + 1];
            float v0 = acc[mi][ni][0] + b0;
            float v1 = acc[mi][ni][1] + b1;
            float v2 = acc[mi][ni][2] + b0;
            float v3 = acc[mi][ni][3] + b1;
            if (RELU) {
                v0 = fmaxf(v0, 0.f); v1 = fmaxf(v1, 0.f);
                v2 = fmaxf(v2, 0.f); v3 = fmaxf(v3, 0.f);
            }
            *(float2*)(C + (size_t)r * N + col)       = make_float2(v0, v1);
            *(float2*)(C + (size_t)(r + 8) * N + col) = make_float2(v2, v3);
        }
    }
}

// ---------------- attention: flash-style, one query per thread ----------------
__global__ __launch_bounds__(128)
void attention_kernel(const float* __restrict__ Q, const float* __restrict__ K,
                      const float* __restrict__ V, const void* __restrict__ mask,
                      float* __restrict__ O)
{
    __shared__ float Ks[32][DK];
    __shared__ float Vs[32][DK];
    __shared__ float Sb[32][128];
    __shared__ float Mk[32];

    const int tid  = threadIdx.x;
    const int h    = blockIdx.y;
    const int b    = blockIdx.z;
    const int qrow = blockIdx.x * 128 + tid;

    const float* qptr = Q + ((size_t)(b * SEQ + qrow)) * D_MODEL + h * DK;
    float q[DK], o[DK];
    #pragma unroll
    for (int d = 0; d < DK; d++) { q[d] = qptr[d]; o[d] = 0.f; }

    float m = -1e30f, l = 0.f;
    const int mode = g_mask_mode;

    for (int kt = 0; kt < SEQ / 32; kt++) {
        #pragma unroll
        for (int it = 0; it < 4; it++) {
            int f = it * 128 + tid;
            int r = f >> 4;
            int c = (f & 15) << 2;
            size_t base = ((size_t)(b * SEQ + kt * 32 + r)) * D_MODEL + h * DK + c;
            *(float4*)&Ks[r][c] = *(const float4*)(K + base);
            *(float4*)&Vs[r][c] = *(const float4*)(V + base);
        }
        if (tid < 32) {
            int bi = b * SEQ + kt * 32 + tid;
            int mv = (mode == 0) ? (((const unsigned int*)mask)[bi] != 0u)
                                 : (((const unsigned char*)mask)[bi] != 0);
            Mk[tid] = mv ? 1.f : 0.f;
        }
        __syncthreads();

        float tmax = -1e30f;
        #pragma unroll 2
        for (int j = 0; j < 32; j++) {
            float s = 0.f;
            #pragma unroll
            for (int d = 0; d < DK; d++) s = fmaf(q[d], Ks[j][d], s);
            s = (Mk[j] != 0.f) ? -1e9f : s * 0.125f;
            Sb[j][tid] = s;
            tmax = fmaxf(tmax, s);
        }

        float mnew = fmaxf(m, tmax);
        float corr = __expf(m - mnew);
        l *= corr;
        #pragma unroll
        for (int d = 0; d < DK; d++) o[d] *= corr;

        #pragma unroll 2
        for (int j = 0; j < 32; j++) {
            float p = __expf(Sb[j][tid] - mnew);
            l += p;
            #pragma unroll
            for (int d = 0; d < DK; d++) o[d] = fmaf(p, Vs[j][d], o[d]);
        }
        m = mnew;
        __syncthreads();
    }

    float inv = 1.f / l;
    float* op = O + ((size_t)(b * SEQ + qrow)) * D_MODEL + h * DK;
    #pragma unroll
    for (int d = 0; d < DK; d++) op[d] = o[d] * inv;
}

// ---------------- residual + LayerNorm (torch: ddof=1, /(std+eps)) ----------------
__global__ __launch_bounds__(256)
void ln_kernel(const float* __restrict__ X, const float* __restrict__ R,
               const float* __restrict__ gamma, const float* __restrict__ beta,
               float* __restrict__ Y)
{
    const int row = blockIdx.x;
    const int tid = threadIdx.x;
    __shared__ float red1[8], red2[8];

    float v[3];
    float s = 0.f, ss = 0.f;
    #pragma unroll
    for (int i = 0; i < 3; i++) {
        int c = i * 256 + tid;
        float a = X[(size_t)row * D_MODEL + c] + R[(size_t)row * D_MODEL + c];
        v[i] = a; s += a; ss += a * a;
    }
    #pragma unroll
    for (int off = 16; off > 0; off >>= 1) {
        s  += __shfl_xor_sync(0xffffffffu, s,  off);
        ss += __shfl_xor_sync(0xffffffffu, ss, off);
    }
    const int wid = tid >> 5, lid = tid & 31;
    if (lid == 0) { red1[wid] = s; red2[wid] = ss; }
    __syncthreads();
    float ts = 0.f, tss = 0.f;
    #pragma unroll
    for (int i = 0; i < 8; i++) { ts += red1[i]; tss += red2[i]; }

    float mean = ts * (1.f / 768.f);
    float var  = (tss - 768.f * mean * mean) * (1.f / 767.f);
    var = fmaxf(var, 0.f);
    float denom = 1.f / (sqrtf(var) + LN_EPS);

    #pragma unroll
    for (int i = 0; i < 3; i++) {
        int c = i * 256 + tid;
        Y[(size_t)row * D_MODEL + c] = gamma[c] * (v[i] - mean) * denom + beta[c];
    }
}

// ---------------- launcher ----------------
extern "C" void kernel_launch(void* const* d_in, const int* in_sizes, int n_in,
                              void* d_out, int out_size)
{
    const float* x   = (const float*)d_in[0];
    const void*  mask=               d_in[1];
    const float* wq  = (const float*)d_in[2];
    const float* bq  = (const float*)d_in[3];
    const float* wk  = (const float*)d_in[4];
    const float* bk  = (const float*)d_in[5];
    const float* wv  = (const float*)d_in[6];
    const float* bv  = (const float*)d_in[7];
    const float* wo  = (const float*)d_in[8];
    const float* bo  = (const float*)d_in[9];
    const float* w1  = (const float*)d_in[10];
    const float* b1  = (const float*)d_in[11];
    const float* w2  = (const float*)d_in[12];
    const float* b2  = (const float*)d_in[13];
    const float* g1  = (const float*)d_in[14];
    const float* be1 = (const float*)d_in[15];
    const float* g2  = (const float*)d_in[16];
    const float* be2 = (const float*)d_in[17];
    float* out = (float*)d_out;

    static float *qb=nullptr,*kb=nullptr,*vb=nullptr,*attn=nullptr,*tmp=nullptr,*x1=nullptr,*ff1=nullptr;
    if (!qb) {
        cudaGetSymbolAddress((void**)&qb,   g_q);
        cudaGetSymbolAddress((void**)&kb,   g_k);
        cudaGetSymbolAddress((void**)&vb,   g_v);
        cudaGetSymbolAddress((void**)&attn, g_attn);
        cudaGetSymbolAddress((void**)&tmp,  g_tmp);
        cudaGetSymbolAddress((void**)&x1,   g_x1);
        cudaGetSymbolAddress((void**)&ff1,  g_ff1);
    }

    detect_mask_kernel<<<1, 1>>>((const unsigned int*)mask);

    dim3 g768(D_MODEL / 128, MTOK / 128);            // (6, 32)
    gemm_mma<0><<<g768, 256>>>(x, wq, bq, qb, MTOK, D_MODEL, D_MODEL);
    gemm_mma<0><<<g768, 256>>>(x, wk, bk, kb, MTOK, D_MODEL, D_MODEL);
    gemm_mma<0><<<g768, 256>>>(x, wv, bv, vb, MTOK, D_MODEL, D_MODEL);

    attention_kernel<<<dim3(SEQ / 128, HEADS, BATCH), 128>>>(qb, kb, vb, mask, attn);

    gemm_mma<0><<<g768, 256>>>(attn, wo, bo, tmp, MTOK, D_MODEL, D_MODEL);
    ln_kernel<<<MTOK, 256>>>(x, tmp, g1, be1, x1);

    gemm_mma<1><<<dim3(DFF / 128, MTOK / 128), 256>>>(x1, w1, b1, ff1, MTOK, DFF, D_MODEL);
    gemm_mma<0><<<g768, 256>>>(ff1, w2, b2, tmp, MTOK, D_MODEL, DFF);
    ln_kernel<<<MTOK, 256>>>(x1, tmp, g2, be2, out);
}

// round 13
// speedup vs baseline: 2.5018x; 1.5596x over previous
#include <cuda_runtime.h>
#include <cstdint>
#include <cstdio>

#define D_MODEL 768
#define HEADS   12
#define DK      64
#define SEQ     2048
#define BATCH   2
#define MTOK    (BATCH*SEQ)   // 4096 token rows
#define DFF     3072
#define LN_EPS  1e-6f

// ---------------- helpers ----------------
__device__ __forceinline__ uint32_t smem_u32(const void* p) {
    uint32_t a;
    asm("{ .reg .u64 t; cvta.to.shared.u64 t, %1; cvt.u32.u64 %0, t; }" : "=r"(a) : "l"(p));
    return a;
}

__device__ __forceinline__ void ldmx4(uint32_t* f, uint32_t addr) {
    asm volatile("ldmatrix.sync.aligned.m8n8.x4.shared.b16 {%0,%1,%2,%3}, [%4];"
                 : "=r"(f[0]), "=r"(f[1]), "=r"(f[2]), "=r"(f[3]) : "r"(addr));
}

__device__ __forceinline__ void ldmx4t(uint32_t* f, uint32_t addr) {
    asm volatile("ldmatrix.sync.aligned.m8n8.x4.trans.shared.b16 {%0,%1,%2,%3}, [%4];"
                 : "=r"(f[0]), "=r"(f[1]), "=r"(f[2]), "=r"(f[3]) : "r"(addr));
}

__device__ __forceinline__ void mma16816(float* d, const uint32_t* a, uint32_t b0, uint32_t b1) {
    asm volatile("mma.sync.aligned.m16n8k16.row.col.f32.bf16.bf16.f32 "
                 "{%0,%1,%2,%3}, {%4,%5,%6,%7}, {%8,%9}, {%0,%1,%2,%3};"
                 : "+f"(d[0]), "+f"(d[1]), "+f"(d[2]), "+f"(d[3])
                 : "r"(a[0]), "r"(a[1]), "r"(a[2]), "r"(a[3]), "r"(b0), "r"(b1));
}

// split 2 fp32 -> packed bf16 hi word + lo word (lo = a - bf16(a))
__device__ __forceinline__ void split2(float a0, float a1, uint32_t& hw, uint32_t& lw) {
    asm("cvt.rn.bf16x2.f32 %0, %1, %2;" : "=r"(hw) : "f"(a1), "f"(a0));
    float h0 = __uint_as_float(hw << 16);
    float h1 = __uint_as_float(hw & 0xffff0000u);
    float l0 = a0 - h0;
    float l1 = a1 - h1;
    asm("cvt.rn.bf16x2.f32 %0, %1, %2;" : "=r"(lw) : "f"(l1), "f"(l0));
}

// ---------------- scratch (device globals: allocation-free) ----------------
__device__ float g_q   [MTOK*D_MODEL];
__device__ float g_k   [MTOK*D_MODEL];
__device__ float g_v   [MTOK*D_MODEL];
__device__ float g_attn[MTOK*D_MODEL];
__device__ float g_tmp [MTOK*D_MODEL];
__device__ float g_x1  [MTOK*D_MODEL];
__device__ float g_ff1 [MTOK*DFF];
__device__ int   g_mask_mode;   // 0 = 4-byte elements, 1 = 1-byte elements

// ---------------- mask dtype detection ----------------
__global__ void detect_mask_kernel(const unsigned int* __restrict__ m)
{
    unsigned ok = 1u;
    for (int i = 0; i < 128; i++) {
        unsigned w = m[i];
        if (w != 0u && w != 1u && w != 0x3F800000u) { ok = 0u; break; }
    }
    g_mask_mode = ok ? 0 : 1;
}

// ================= HMMA GEMM (mma.sync bf16, 3-term split) =================
#define MAT_BYTES 6144          // 128*48
#define BUF_BYTES (4*MAT_BYTES) // 24KB
#define STRIDE    48

template<int RELU>
__global__ __launch_bounds__(256, 1)
void gemm_mma(const float* __restrict__ A, const float* __restrict__ B,
              const float* __restrict__ bias, float* __restrict__ C,
              int M, int N, int K)
{
    __shared__ __align__(16) unsigned char sm[2 * BUF_BYTES];   // 48KB

    const int tid  = threadIdx.x;
    const int lane = tid & 31;
    const int wid  = tid >> 5;
    const int m0 = blockIdx.y * 128;
    const int n0 = blockIdx.x * 128;
    const int wm = (wid & 1) * 64;
    const int wn = (wid >> 1) * 32;
    const uint32_t sbase = smem_u32(sm);

    float acc[4][4][4];
    #pragma unroll
    for (int i = 0; i < 4; i++)
        #pragma unroll
        for (int j = 0; j < 4; j++)
            #pragma unroll
            for (int k = 0; k < 4; k++) acc[i][j][k] = 0.f;

    const int r1  = tid >> 2;
    const int c4a = (tid & 3) << 2;

    const float* Ap = A + (size_t)m0 * K;
    const float* Bp = B + (size_t)n0 * K;

    float4 ra0, ra1, rb0, rb1;
    ra0 = *(const float4*)(Ap + (size_t)r1 * K + c4a);
    ra1 = *(const float4*)(Ap + (size_t)(r1 + 64) * K + c4a);
    rb0 = *(const float4*)(Bp + (size_t)r1 * K + c4a);
    rb1 = *(const float4*)(Bp + (size_t)(r1 + 64) * K + c4a);

    const int  arow0 = wm + (lane & 15);
    const uint32_t acolb = (uint32_t)((lane >> 4) << 4);
    const int  g     = lane >> 3;
    const int  brow0 = wn + ((g >> 1) << 3) + (lane & 7);
    const uint32_t bcolb = (uint32_t)((g & 1) << 4);

    const int NC = K >> 4;
    for (int c = 0; c < NC; c++) {
        const uint32_t bufb = sbase + (uint32_t)(c & 1) * BUF_BYTES;
        unsigned char* bufp = sm + (c & 1) * BUF_BYTES;

        {
            uint32_t h, l, h2, l2;
            uint32_t o1 = (uint32_t)(r1 * STRIDE + (c4a << 1));
            uint32_t o2 = (uint32_t)((r1 + 64) * STRIDE + (c4a << 1));

            split2(ra0.x, ra0.y, h, l); split2(ra0.z, ra0.w, h2, l2);
            *(uint32_t*)(bufp + o1)                 = h;
            *(uint32_t*)(bufp + o1 + 4)             = h2;
            *(uint32_t*)(bufp + MAT_BYTES + o1)     = l;
            *(uint32_t*)(bufp + MAT_BYTES + o1 + 4) = l2;

            split2(ra1.x, ra1.y, h, l); split2(ra1.z, ra1.w, h2, l2);
            *(uint32_t*)(bufp + o2)                 = h;
            *(uint32_t*)(bufp + o2 + 4)             = h2;
            *(uint32_t*)(bufp + MAT_BYTES + o2)     = l;
            *(uint32_t*)(bufp + MAT_BYTES + o2 + 4) = l2;

            split2(rb0.x, rb0.y, h, l); split2(rb0.z, rb0.w, h2, l2);
            *(uint32_t*)(bufp + 2*MAT_BYTES + o1)     = h;
            *(uint32_t*)(bufp + 2*MAT_BYTES + o1 + 4) = h2;
            *(uint32_t*)(bufp + 3*MAT_BYTES + o1)     = l;
            *(uint32_t*)(bufp + 3*MAT_BYTES + o1 + 4) = l2;

            split2(rb1.x, rb1.y, h, l); split2(rb1.z, rb1.w, h2, l2);
            *(uint32_t*)(bufp + 2*MAT_BYTES + o2)     = h;
            *(uint32_t*)(bufp + 2*MAT_BYTES + o2 + 4) = h2;
            *(uint32_t*)(bufp + 3*MAT_BYTES + o2)     = l;
            *(uint32_t*)(bufp + 3*MAT_BYTES + o2 + 4) = l2;
        }

        if (c + 1 < NC) {
            const float* An = Ap + (size_t)(c + 1) * 16;
            const float* Bn = Bp + (size_t)(c + 1) * 16;
            ra0 = *(const float4*)(An + (size_t)r1 * K + c4a);
            ra1 = *(const float4*)(An + (size_t)(r1 + 64) * K + c4a);
            rb0 = *(const float4*)(Bn + (size_t)r1 * K + c4a);
            rb1 = *(const float4*)(Bn + (size_t)(r1 + 64) * K + c4a);
        }

        __syncthreads();

        uint32_t Ah[4][4], Al[4][4], Bh[2][4], Bl[2][4];
        #pragma unroll
        for (int mi = 0; mi < 4; mi++) {
            uint32_t ao = bufb + (uint32_t)((arow0 + mi * 16) * STRIDE) + acolb;
            ldmx4(Ah[mi], ao);
            ldmx4(Al[mi], ao + MAT_BYTES);
        }
        {
            uint32_t bo = bufb + 2*MAT_BYTES + (uint32_t)(brow0 * STRIDE) + bcolb;
            ldmx4(Bh[0], bo);
            ldmx4(Bh[1], bo + 16 * STRIDE);
            ldmx4(Bl[0], bo + MAT_BYTES);
            ldmx4(Bl[1], bo + MAT_BYTES + 16 * STRIDE);
        }

        #pragma unroll
        for (int mi = 0; mi < 4; mi++) {
            #pragma unroll
            for (int ni = 0; ni < 4; ni++) {
                uint32_t bh0 = Bh[ni >> 1][(ni & 1) * 2];
                uint32_t bh1 = Bh[ni >> 1][(ni & 1) * 2 + 1];
                uint32_t bl0 = Bl[ni >> 1][(ni & 1) * 2];
                uint32_t bl1 = Bl[ni >> 1][(ni & 1) * 2 + 1];
                mma16816(acc[mi][ni], Ah[mi], bh0, bh1);
                mma16816(acc[mi][ni], Ah[mi], bl0, bl1);
                mma16816(acc[mi][ni], Al[mi], bh0, bh1);
            }
        }
    }

    #pragma unroll
    for (int mi = 0; mi < 4; mi++) {
        int r = m0 + wm + mi * 16 + (lane >> 2);
        #pragma unroll
        for (int ni = 0; ni < 4; ni++) {
            int col = n0 + wn + ni * 8 + (lane & 3) * 2;
            float b0 = bias[col], b1 = bias[col + 1];
            float v0 = acc[mi][ni][0] + b0;
            float v1 = acc[mi][ni][1] + b1;
            float v2 = acc[mi][ni][2] + b0;
            float v3 = acc[mi][ni][3] + b1;
            if (RELU) {
                v0 = fmaxf(v0, 0.f); v1 = fmaxf(v1, 0.f);
                v2 = fmaxf(v2, 0.f); v3 = fmaxf(v3, 0.f);
            }
            *(float2*)(C + (size_t)r * N + col)       = make_float2(v0, v1);
            *(float2*)(C + (size_t)(r + 8) * N + col) = make_float2(v2, v3);
        }
    }
}

// ================= HMMA flash attention =================
// CTA: 64 queries x one (b,h). 4 warps, warp w owns query rows 16w..16w+15.
// Key tiles of 64, online softmax on fragments, 3-term bf16 splits for
// QK^T and PV. smem tiles: 64 rows x 144B (64 bf16 + 16B pad).
#define STRA 144
#define AQHI 0
#define AQLO 9216
#define AKHI 18432
#define AKLO 27648
#define AVHI 36864
#define AVLO 46080
#define AMSK 55296
#define ATT_SMEM (AMSK + 64*4)

__global__ __launch_bounds__(128, 1)
void attention_mma(const float* __restrict__ Q, const float* __restrict__ K,
                   const float* __restrict__ V, const void* __restrict__ mask,
                   float* __restrict__ O)
{
    extern __shared__ char smem[];
    const uint32_t sb = smem_u32(smem);
    const int tid  = threadIdx.x;
    const int lane = tid & 31;
    const int wid  = tid >> 5;
    const int h  = blockIdx.y;
    const int b  = blockIdx.z;
    const int q0 = blockIdx.x * 64;          // first query row of tile
    const int mode = g_mask_mode;

    // ---- load + split Q tile (64x64) ----
    {
        const int r  = tid >> 1;             // 0..63
        const int c8 = (tid & 1) * 32;       // two 32-col halves
        #pragma unroll
        for (int i = 0; i < 8; i++) {
            int c4 = c8 + i * 4;
            float4 v = *(const float4*)(Q + ((size_t)(b * SEQ + q0 + r)) * D_MODEL + h * DK + c4);
            uint32_t hh, ll, h2, l2;
            split2(v.x, v.y, hh, ll); split2(v.z, v.w, h2, l2);
            *(uint2*)(smem + AQHI + r * STRA + c4 * 2) = make_uint2(hh, h2);
            *(uint2*)(smem + AQLO + r * STRA + c4 * 2) = make_uint2(ll, l2);
        }
    }
    __syncthreads();

    // ---- Q fragments (persistent) ----
    uint32_t Aqh[4][4], Aql[4][4];
    {
        const int arow = 16 * wid + (lane & 15);
        const uint32_t acolb = (uint32_t)((lane >> 4) << 4);
        #pragma unroll
        for (int kf = 0; kf < 4; kf++) {
            uint32_t ao = sb + (uint32_t)(arow * STRA + kf * 32) + acolb;
            ldmx4(Aqh[kf], ao + AQHI);
            ldmx4(Aql[kf], ao + AQLO);
        }
    }

    float Oa[8][4];
    #pragma unroll
    for (int i = 0; i < 8; i++)
        #pragma unroll
        for (int j = 0; j < 4; j++) Oa[i][j] = 0.f;
    float m_r = -1e30f, m_r2 = -1e30f, l_r = 0.f, l_r2 = 0.f;

    // B-fragment addressing (same as gemm, validated)
    const int gB = lane >> 3;
    const int browB = ((gB >> 1) << 3) + (lane & 7);
    const uint32_t bcolB = (uint32_t)((gB & 1) << 4);
    // V-trans addressing
    const int vrowB = ((gB & 1) << 3) + (lane & 7);
    const uint32_t vcolB = (uint32_t)((gB >> 1) << 4);

    for (int kt = 0; kt < SEQ / 64; kt++) {
        __syncthreads();   // prior tile's smem reads complete

        // ---- load + split K,V tiles; mask ----
        {
            const int r  = tid >> 1;
            const int c8 = (tid & 1) * 32;
            #pragma unroll
            for (int i = 0; i < 8; i++) {
                int c4 = c8 + i * 4;
                size_t base = ((size_t)(b * SEQ + kt * 64 + r)) * D_MODEL + h * DK + c4;
                float4 kv = *(const float4*)(K + base);
                uint32_t hh, ll, h2, l2;
                split2(kv.x, kv.y, hh, ll); split2(kv.z, kv.w, h2, l2);
                *(uint2*)(smem + AKHI + r * STRA + c4 * 2) = make_uint2(hh, h2);
                *(uint2*)(smem + AKLO + r * STRA + c4 * 2) = make_uint2(ll, l2);
                float4 vv = *(const float4*)(V + base);
                split2(vv.x, vv.y, hh, ll); split2(vv.z, vv.w, h2, l2);
                *(uint2*)(smem + AVHI + r * STRA + c4 * 2) = make_uint2(hh, h2);
                *(uint2*)(smem + AVLO + r * STRA + c4 * 2) = make_uint2(ll, l2);
            }
            if (tid < 64) {
                int bi = b * SEQ + kt * 64 + tid;
                int mv = (mode == 0) ? (((const unsigned int*)mask)[bi] != 0u)
                                     : (((const unsigned char*)mask)[bi] != 0);
                ((float*)(smem + AMSK))[tid] = mv ? 1.f : 0.f;
            }
        }
        __syncthreads();

        // ---- S = Q K^T (3-term split) ----
        float S[8][4];
        #pragma unroll
        for (int i = 0; i < 8; i++)
            #pragma unroll
            for (int j = 0; j < 4; j++) S[i][j] = 0.f;

        #pragma unroll
        for (int kf = 0; kf < 4; kf++) {
            uint32_t Bh[4][4], Bl[4][4];
            #pragma unroll
            for (int nf16 = 0; nf16 < 4; nf16++) {
                uint32_t bo = sb + (uint32_t)((nf16 * 16 + browB) * STRA + kf * 32) + bcolB;
                ldmx4(Bh[nf16], bo + AKHI);
                ldmx4(Bl[nf16], bo + AKLO);
            }
            #pragma unroll
            for (int nf16 = 0; nf16 < 4; nf16++) {
                #pragma unroll
                for (int hf = 0; hf < 2; hf++) {
                    float* sp = S[nf16 * 2 + hf];
                    uint32_t bh0 = Bh[nf16][hf * 2], bh1 = Bh[nf16][hf * 2 + 1];
                    uint32_t bl0 = Bl[nf16][hf * 2], bl1 = Bl[nf16][hf * 2 + 1];
                    mma16816(sp, Aqh[kf], bh0, bh1);
                    mma16816(sp, Aqh[kf], bl0, bl1);
                    mma16816(sp, Aql[kf], bh0, bh1);
                }
            }
        }

        // ---- mask + scale, tile row max ----
        const float* mk = (const float*)(smem + AMSK);
        float tmax_r = -1e30f, tmax_r2 = -1e30f;
        #pragma unroll
        for (int nf = 0; nf < 8; nf++) {
            int col = nf * 8 + (lane & 3) * 2;
            float m0v = mk[col], m1v = mk[col + 1];
            S[nf][0] = (m0v != 0.f) ? -1e9f : S[nf][0] * 0.125f;
            S[nf][1] = (m1v != 0.f) ? -1e9f : S[nf][1] * 0.125f;
            S[nf][2] = (m0v != 0.f) ? -1e9f : S[nf][2] * 0.125f;
            S[nf][3] = (m1v != 0.f) ? -1e9f : S[nf][3] * 0.125f;
            tmax_r  = fmaxf(tmax_r,  fmaxf(S[nf][0], S[nf][1]));
            tmax_r2 = fmaxf(tmax_r2, fmaxf(S[nf][2], S[nf][3]));
        }
        #pragma unroll
        for (int d = 1; d <= 2; d <<= 1) {
            tmax_r  = fmaxf(tmax_r,  __shfl_xor_sync(0xffffffffu, tmax_r,  d));
            tmax_r2 = fmaxf(tmax_r2, __shfl_xor_sync(0xffffffffu, tmax_r2, d));
        }

        float mnew_r  = fmaxf(m_r,  tmax_r);
        float mnew_r2 = fmaxf(m_r2, tmax_r2);
        float corr_r  = __expf(m_r  - mnew_r);
        float corr_r2 = __expf(m_r2 - mnew_r2);
        l_r *= corr_r; l_r2 *= corr_r2;
        #pragma unroll
        for (int nf = 0; nf < 8; nf++) {
            Oa[nf][0] *= corr_r;  Oa[nf][1] *= corr_r;
            Oa[nf][2] *= corr_r2; Oa[nf][3] *= corr_r2;
        }
        m_r = mnew_r; m_r2 = mnew_r2;

        // ---- exp, accumulate l, build P fragments (hi/lo) ----
        uint32_t Ph[4][4], Pl[4][4];
        #pragma unroll
        for (int kf = 0; kf < 4; kf++) {
            float p00 = __expf(S[2*kf][0]   - mnew_r);
            float p01 = __expf(S[2*kf][1]   - mnew_r);
            float p02 = __expf(S[2*kf][2]   - mnew_r2);
            float p03 = __expf(S[2*kf][3]   - mnew_r2);
            float p10 = __expf(S[2*kf+1][0] - mnew_r);
            float p11 = __expf(S[2*kf+1][1] - mnew_r);
            float p12 = __expf(S[2*kf+1][2] - mnew_r2);
            float p13 = __expf(S[2*kf+1][3] - mnew_r2);
            l_r  += p00 + p01 + p10 + p11;
            l_r2 += p02 + p03 + p12 + p13;
            split2(p00, p01, Ph[kf][0], Pl[kf][0]);   // a0: row r,  k lo
            split2(p02, p03, Ph[kf][1], Pl[kf][1]);   // a1: row r+8
            split2(p10, p11, Ph[kf][2], Pl[kf][2]);   // a2: row r,  k hi
            split2(p12, p13, Ph[kf][3], Pl[kf][3]);   // a3: row r+8
        }

        // ---- O += P V  (V^T fragments via ldmatrix.trans) ----
        #pragma unroll
        for (int kf = 0; kf < 4; kf++) {
            uint32_t Vh[4][4], Vl[4][4];
            #pragma unroll
            for (int df = 0; df < 4; df++) {
                uint32_t vo = sb + (uint32_t)((kf * 16 + vrowB) * STRA + df * 32) + vcolB;
                ldmx4t(Vh[df], vo + AVHI);
                ldmx4t(Vl[df], vo + AVLO);
            }
            #pragma unroll
            for (int df = 0; df < 4; df++) {
                #pragma unroll
                for (int hf = 0; hf < 2; hf++) {
                    float* op = Oa[df * 2 + hf];
                    uint32_t bh0 = Vh[df][hf * 2], bh1 = Vh[df][hf * 2 + 1];
                    uint32_t bl0 = Vl[df][hf * 2], bl1 = Vl[df][hf * 2 + 1];
                    mma16816(op, Ph[kf], bh0, bh1);
                    mma16816(op, Ph[kf], bl0, bl1);
                    mma16816(op, Pl[kf], bh0, bh1);
                }
            }
        }
    }

    // ---- finalize: reduce l, normalize, store ----
    #pragma unroll
    for (int d = 1; d <= 2; d <<= 1) {
        l_r  += __shfl_xor_sync(0xffffffffu, l_r,  d);
        l_r2 += __shfl_xor_sync(0xffffffffu, l_r2, d);
    }
    float inv_r = 1.f / l_r, inv_r2 = 1.f / l_r2;

    const int qa = b * SEQ + q0 + 16 * wid + (lane >> 2);
    const int qb2 = qa + 8;
    #pragma unroll
    for (int nf = 0; nf < 8; nf++) {
        int col = h * DK + nf * 8 + (lane & 3) * 2;
        *(float2*)(O + (size_t)qa  * D_MODEL + col) = make_float2(Oa[nf][0] * inv_r,  Oa[nf][1] * inv_r);
        *(float2*)(O + (size_t)qb2 * D_MODEL + col) = make_float2(Oa[nf][2] * inv_r2, Oa[nf][3] * inv_r2);
    }
}

// ---------------- residual + LayerNorm (torch: ddof=1, /(std+eps)) ----------------
__global__ __launch_bounds__(256)
void ln_kernel(const float* __restrict__ X, const float* __restrict__ R,
               const float* __restrict__ gamma, const float* __restrict__ beta,
               float* __restrict__ Y)
{
    const int row = blockIdx.x;
    const int tid = threadIdx.x;
    __shared__ float red1[8], red2[8];

    float v[3];
    float s = 0.f, ss = 0.f;
    #pragma unroll
    for (int i = 0; i < 3; i++) {
        int c = i * 256 + tid;
        float a = X[(size_t)row * D_MODEL + c] + R[(size_t)row * D_MODEL + c];
        v[i] = a; s += a; ss += a * a;
    }
    #pragma unroll
    for (int off = 16; off > 0; off >>= 1) {
        s  += __shfl_xor_sync(0xffffffffu, s,  off);
        ss += __shfl_xor_sync(0xffffffffu, ss, off);
    }
    const int wid = tid >> 5, lid = tid & 31;
    if (lid == 0) { red1[wid] = s; red2[wid] = ss; }
    __syncthreads();
    float ts = 0.f, tss = 0.f;
    #pragma unroll
    for (int i = 0; i < 8; i++) { ts += red1[i]; tss += red2[i]; }

    float mean = ts * (1.f / 768.f);
    float var  = (tss - 768.f * mean * mean) * (1.f / 767.f);
    var = fmaxf(var, 0.f);
    float denom = 1.f / (sqrtf(var) + LN_EPS);

    #pragma unroll
    for (int i = 0; i < 3; i++) {
        int c = i * 256 + tid;
        Y[(size_t)row * D_MODEL + c] = gamma[c] * (v[i] - mean) * denom + beta[c];
    }
}

// ---------------- launcher ----------------
extern "C" void kernel_launch(void* const* d_in, const int* in_sizes, int n_in,
                              void* d_out, int out_size)
{
    const float* x   = (const float*)d_in[0];
    const void*  mask=               d_in[1];
    const float* wq  = (const float*)d_in[2];
    const float* bq  = (const float*)d_in[3];
    const float* wk  = (const float*)d_in[4];
    const float* bk  = (const float*)d_in[5];
    const float* wv  = (const float*)d_in[6];
    const float* bv  = (const float*)d_in[7];
    const float* wo  = (const float*)d_in[8];
    const float* bo  = (const float*)d_in[9];
    const float* w1  = (const float*)d_in[10];
    const float* b1  = (const float*)d_in[11];
    const float* w2  = (const float*)d_in[12];
    const float* b2  = (const float*)d_in[13];
    const float* g1  = (const float*)d_in[14];
    const float* be1 = (const float*)d_in[15];
    const float* g2  = (const float*)d_in[16];
    const float* be2 = (const float*)d_in[17];
    float* out = (float*)d_out;

    static float *qb=nullptr,*kb=nullptr,*vb=nullptr,*attn=nullptr,*tmp=nullptr,*x1=nullptr,*ff1=nullptr;
    if (!qb) {
        cudaGetSymbolAddress((void**)&qb,   g_q);
        cudaGetSymbolAddress((void**)&kb,   g_k);
        cudaGetSymbolAddress((void**)&vb,   g_v);
        cudaGetSymbolAddress((void**)&attn, g_attn);
        cudaGetSymbolAddress((void**)&tmp,  g_tmp);
        cudaGetSymbolAddress((void**)&x1,   g_x1);
        cudaGetSymbolAddress((void**)&ff1,  g_ff1);
        cudaFuncSetAttribute(attention_mma, cudaFuncAttributeMaxDynamicSharedMemorySize, ATT_SMEM);
    }

    detect_mask_kernel<<<1, 1>>>((const unsigned int*)mask);

    dim3 g768(D_MODEL / 128, MTOK / 128);            // (6, 32)
    gemm_mma<0><<<g768, 256>>>(x, wq, bq, qb, MTOK, D_MODEL, D_MODEL);
    gemm_mma<0><<<g768, 256>>>(x, wk, bk, kb, MTOK, D_MODEL, D_MODEL);
    gemm_mma<0><<<g768, 256>>>(x, wv, bv, vb, MTOK, D_MODEL, D_MODEL);

    attention_mma<<<dim3(SEQ / 64, HEADS, BATCH), 128, ATT_SMEM>>>(qb, kb, vb, mask, attn);

    gemm_mma<0><<<g768, 256>>>(attn, wo, bo, tmp, MTOK, D_MODEL, D_MODEL);
    ln_kernel<<<MTOK, 256>>>(x, tmp, g1, be1, x1);

    gemm_mma<1><<<dim3(DFF / 128, MTOK / 128), 256>>>(x1, w1, b1, ff1, MTOK, DFF, D_MODEL);
    gemm_mma<0><<<g768, 256>>>(ff1, w2, b2, tmp, MTOK, D_MODEL, DFF);
    ln_kernel<<<MTOK, 256>>>(x1, tmp, g2, be2, out);
}

// round 16
// speedup vs baseline: 2.7450x; 1.0972x over previous
#include <cuda_runtime.h>
#include <cstdint>
#include <cstdio>

#define D_MODEL 768
#define HEADS   12
#define DK      64
#define SEQ     2048
#define BATCH   2
#define MTOK    (BATCH*SEQ)   // 4096 token rows
#define DFF     3072
#define LN_EPS  1e-6f

// ---------------- helpers ----------------
__device__ __forceinline__ uint32_t smem_u32(const void* p) {
    uint32_t a;
    asm("{ .reg .u64 t; cvta.to.shared.u64 t, %1; cvt.u32.u64 %0, t; }" : "=r"(a) : "l"(p));
    return a;
}

__device__ __forceinline__ void ldmx4(uint32_t* f, uint32_t addr) {
    asm volatile("ldmatrix.sync.aligned.m8n8.x4.shared.b16 {%0,%1,%2,%3}, [%4];"
                 : "=r"(f[0]), "=r"(f[1]), "=r"(f[2]), "=r"(f[3]) : "r"(addr));
}

__device__ __forceinline__ void ldmx4t(uint32_t* f, uint32_t addr) {
    asm volatile("ldmatrix.sync.aligned.m8n8.x4.trans.shared.b16 {%0,%1,%2,%3}, [%4];"
                 : "=r"(f[0]), "=r"(f[1]), "=r"(f[2]), "=r"(f[3]) : "r"(addr));
}

__device__ __forceinline__ void mma16816(float* d, const uint32_t* a, uint32_t b0, uint32_t b1) {
    asm volatile("mma.sync.aligned.m16n8k16.row.col.f32.bf16.bf16.f32 "
                 "{%0,%1,%2,%3}, {%4,%5,%6,%7}, {%8,%9}, {%0,%1,%2,%3};"
                 : "+f"(d[0]), "+f"(d[1]), "+f"(d[2]), "+f"(d[3])
                 : "r"(a[0]), "r"(a[1]), "r"(a[2]), "r"(a[3]), "r"(b0), "r"(b1));
}

// split 2 fp32 -> packed bf16 hi word + lo word (lo = a - bf16(a))
__device__ __forceinline__ void split2(float a0, float a1, uint32_t& hw, uint32_t& lw) {
    asm("cvt.rn.bf16x2.f32 %0, %1, %2;" : "=r"(hw) : "f"(a1), "f"(a0));
    float h0 = __uint_as_float(hw << 16);
    float h1 = __uint_as_float(hw & 0xffff0000u);
    float l0 = a0 - h0;
    float l1 = a1 - h1;
    asm("cvt.rn.bf16x2.f32 %0, %1, %2;" : "=r"(lw) : "f"(l1), "f"(l0));
}

// ---------------- scratch (device globals: allocation-free) ----------------
__device__ float g_q   [MTOK*D_MODEL];
__device__ float g_k   [MTOK*D_MODEL];
__device__ float g_v   [MTOK*D_MODEL];
__device__ float g_attn[MTOK*D_MODEL];
__device__ float g_tmp [MTOK*D_MODEL];
__device__ float g_x1  [MTOK*D_MODEL];
__device__ float g_ff1 [MTOK*DFF];
__device__ int   g_mask_mode;   // 0 = 4-byte elements, 1 = 1-byte elements

// ---------------- mask dtype detection ----------------
__global__ void detect_mask_kernel(const unsigned int* __restrict__ m)
{
    unsigned ok = 1u;
    for (int i = 0; i < 128; i++) {
        unsigned w = m[i];
        if (w != 0u && w != 1u && w != 0x3F800000u) { ok = 0u; break; }
    }
    g_mask_mode = ok ? 0 : 1;
}

// ================= HMMA GEMM (mma.sync bf16, 3-term split) =================
// 2 CTAs/SM: A-fragments loaded per-mi to cut register liveness under 128.
#define MAT_BYTES 6144          // 128*48
#define BUF_BYTES (4*MAT_BYTES) // 24KB
#define STRIDE    48

template<int RELU>
__global__ __launch_bounds__(256, 2)
void gemm_mma(const float* __restrict__ A, const float* __restrict__ B,
              const float* __restrict__ bias, float* __restrict__ C,
              int M, int N, int K)
{
    __shared__ __align__(16) unsigned char sm[2 * BUF_BYTES];   // 48KB

    const int tid  = threadIdx.x;
    const int lane = tid & 31;
    const int wid  = tid >> 5;
    const int m0 = blockIdx.y * 128;
    const int n0 = blockIdx.x * 128;
    const int wm = (wid & 1) * 64;
    const int wn = (wid >> 1) * 32;
    const uint32_t sbase = smem_u32(sm);

    float acc[4][4][4];
    #pragma unroll
    for (int i = 0; i < 4; i++)
        #pragma unroll
        for (int j = 0; j < 4; j++)
            #pragma unroll
            for (int k = 0; k < 4; k++) acc[i][j][k] = 0.f;

    const int r1  = tid >> 2;
    const int c4a = (tid & 3) << 2;

    const float* Ap = A + (size_t)m0 * K;
    const float* Bp = B + (size_t)n0 * K;

    float4 ra0, ra1, rb0, rb1;
    ra0 = *(const float4*)(Ap + (size_t)r1 * K + c4a);
    ra1 = *(const float4*)(Ap + (size_t)(r1 + 64) * K + c4a);
    rb0 = *(const float4*)(Bp + (size_t)r1 * K + c4a);
    rb1 = *(const float4*)(Bp + (size_t)(r1 + 64) * K + c4a);

    const int  arow0 = wm + (lane & 15);
    const uint32_t acolb = (uint32_t)((lane >> 4) << 4);
    const int  g     = lane >> 3;
    const int  brow0 = wn + ((g >> 1) << 3) + (lane & 7);
    const uint32_t bcolb = (uint32_t)((g & 1) << 4);

    const int NC = K >> 4;
    for (int c = 0; c < NC; c++) {
        const uint32_t bufb = sbase + (uint32_t)(c & 1) * BUF_BYTES;
        unsigned char* bufp = sm + (c & 1) * BUF_BYTES;

        {
            uint32_t h, l, h2, l2;
            uint32_t o1 = (uint32_t)(r1 * STRIDE + (c4a << 1));
            uint32_t o2 = (uint32_t)((r1 + 64) * STRIDE + (c4a << 1));

            split2(ra0.x, ra0.y, h, l); split2(ra0.z, ra0.w, h2, l2);
            *(uint32_t*)(bufp + o1)                 = h;
            *(uint32_t*)(bufp + o1 + 4)             = h2;
            *(uint32_t*)(bufp + MAT_BYTES + o1)     = l;
            *(uint32_t*)(bufp + MAT_BYTES + o1 + 4) = l2;

            split2(ra1.x, ra1.y, h, l); split2(ra1.z, ra1.w, h2, l2);
            *(uint32_t*)(bufp + o2)                 = h;
            *(uint32_t*)(bufp + o2 + 4)             = h2;
            *(uint32_t*)(bufp + MAT_BYTES + o2)     = l;
            *(uint32_t*)(bufp + MAT_BYTES + o2 + 4) = l2;

            split2(rb0.x, rb0.y, h, l); split2(rb0.z, rb0.w, h2, l2);
            *(uint32_t*)(bufp + 2*MAT_BYTES + o1)     = h;
            *(uint32_t*)(bufp + 2*MAT_BYTES + o1 + 4) = h2;
            *(uint32_t*)(bufp + 3*MAT_BYTES + o1)     = l;
            *(uint32_t*)(bufp + 3*MAT_BYTES + o1 + 4) = l2;

            split2(rb1.x, rb1.y, h, l); split2(rb1.z, rb1.w, h2, l2);
            *(uint32_t*)(bufp + 2*MAT_BYTES + o2)     = h;
            *(uint32_t*)(bufp + 2*MAT_BYTES + o2 + 4) = h2;
            *(uint32_t*)(bufp + 3*MAT_BYTES + o2)     = l;
            *(uint32_t*)(bufp + 3*MAT_BYTES + o2 + 4) = l2;
        }

        if (c + 1 < NC) {
            const float* An = Ap + (size_t)(c + 1) * 16;
            const float* Bn = Bp + (size_t)(c + 1) * 16;
            ra0 = *(const float4*)(An + (size_t)r1 * K + c4a);
            ra1 = *(const float4*)(An + (size_t)(r1 + 64) * K + c4a);
            rb0 = *(const float4*)(Bn + (size_t)r1 * K + c4a);
            rb1 = *(const float4*)(Bn + (size_t)(r1 + 64) * K + c4a);
        }

        __syncthreads();

        // B fragments once per chunk; A fragments per-mi (lower reg pressure)
        uint32_t Bh[2][4], Bl[2][4];
        {
            uint32_t bo = bufb + 2*MAT_BYTES + (uint32_t)(brow0 * STRIDE) + bcolb;
            ldmx4(Bh[0], bo);
            ldmx4(Bh[1], bo + 16 * STRIDE);
            ldmx4(Bl[0], bo + MAT_BYTES);
            ldmx4(Bl[1], bo + MAT_BYTES + 16 * STRIDE);
        }

        #pragma unroll
        for (int mi = 0; mi < 4; mi++) {
            uint32_t Ah[4], Al[4];
            uint32_t ao = bufb + (uint32_t)((arow0 + mi * 16) * STRIDE) + acolb;
            ldmx4(Ah, ao);
            ldmx4(Al, ao + MAT_BYTES);
            #pragma unroll
            for (int ni = 0; ni < 4; ni++) {
                uint32_t bh0 = Bh[ni >> 1][(ni & 1) * 2];
                uint32_t bh1 = Bh[ni >> 1][(ni & 1) * 2 + 1];
                uint32_t bl0 = Bl[ni >> 1][(ni & 1) * 2];
                uint32_t bl1 = Bl[ni >> 1][(ni & 1) * 2 + 1];
                mma16816(acc[mi][ni], Ah, bh0, bh1);
                mma16816(acc[mi][ni], Ah, bl0, bl1);
                mma16816(acc[mi][ni], Al, bh0, bh1);
            }
        }
    }

    #pragma unroll
    for (int mi = 0; mi < 4; mi++) {
        int r = m0 + wm + mi * 16 + (lane >> 2);
        #pragma unroll
        for (int ni = 0; ni < 4; ni++) {
            int col = n0 + wn + ni * 8 + (lane & 3) * 2;
            float b0 = bias[col], b1 = bias[col + 1];
            float v0 = acc[mi][ni][0] + b0;
            float v1 = acc[mi][ni][1] + b1;
            float v2 = acc[mi][ni][2] + b0;
            float v3 = acc[mi][ni][3] + b1;
            if (RELU) {
                v0 = fmaxf(v0, 0.f); v1 = fmaxf(v1, 0.f);
                v2 = fmaxf(v2, 0.f); v3 = fmaxf(v3, 0.f);
            }
            *(float2*)(C + (size_t)r * N + col)       = make_float2(v0, v1);
            *(float2*)(C + (size_t)(r + 8) * N + col) = make_float2(v2, v3);
        }
    }
}

// ================= HMMA flash attention =================
// CTA: 64 queries x one (b,h). 4 warps, warp w owns query rows 16w..16w+15.
#define STRA 144
#define AQHI 0
#define AQLO 9216
#define AKHI 18432
#define AKLO 27648
#define AVHI 36864
#define AVLO 46080
#define AMSK 55296
#define ATT_SMEM (AMSK + 64*4)

__global__ __launch_bounds__(128, 1)
void attention_mma(const float* __restrict__ Q, const float* __restrict__ K,
                   const float* __restrict__ V, const void* __restrict__ mask,
                   float* __restrict__ O)
{
    extern __shared__ char smem[];
    const uint32_t sb = smem_u32(smem);
    const int tid  = threadIdx.x;
    const int lane = tid & 31;
    const int wid  = tid >> 5;
    const int h  = blockIdx.y;
    const int b  = blockIdx.z;
    const int q0 = blockIdx.x * 64;
    const int mode = g_mask_mode;

    {
        const int r  = tid >> 1;
        const int c8 = (tid & 1) * 32;
        #pragma unroll
        for (int i = 0; i < 8; i++) {
            int c4 = c8 + i * 4;
            float4 v = *(const float4*)(Q + ((size_t)(b * SEQ + q0 + r)) * D_MODEL + h * DK + c4);
            uint32_t hh, ll, h2, l2;
            split2(v.x, v.y, hh, ll); split2(v.z, v.w, h2, l2);
            *(uint2*)(smem + AQHI + r * STRA + c4 * 2) = make_uint2(hh, h2);
            *(uint2*)(smem + AQLO + r * STRA + c4 * 2) = make_uint2(ll, l2);
        }
    }
    __syncthreads();

    uint32_t Aqh[4][4], Aql[4][4];
    {
        const int arow = 16 * wid + (lane & 15);
        const uint32_t acolb = (uint32_t)((lane >> 4) << 4);
        #pragma unroll
        for (int kf = 0; kf < 4; kf++) {
            uint32_t ao = sb + (uint32_t)(arow * STRA + kf * 32) + acolb;
            ldmx4(Aqh[kf], ao + AQHI);
            ldmx4(Aql[kf], ao + AQLO);
        }
    }

    float Oa[8][4];
    #pragma unroll
    for (int i = 0; i < 8; i++)
        #pragma unroll
        for (int j = 0; j < 4; j++) Oa[i][j] = 0.f;
    float m_r = -1e30f, m_r2 = -1e30f, l_r = 0.f, l_r2 = 0.f;

    const int gB = lane >> 3;
    const int browB = ((gB >> 1) << 3) + (lane & 7);
    const uint32_t bcolB = (uint32_t)((gB & 1) << 4);
    const int vrowB = ((gB & 1) << 3) + (lane & 7);
    const uint32_t vcolB = (uint32_t)((gB >> 1) << 4);

    for (int kt = 0; kt < SEQ / 64; kt++) {
        __syncthreads();

        {
            const int r  = tid >> 1;
            const int c8 = (tid & 1) * 32;
            #pragma unroll
            for (int i = 0; i < 8; i++) {
                int c4 = c8 + i * 4;
                size_t base = ((size_t)(b * SEQ + kt * 64 + r)) * D_MODEL + h * DK + c4;
                float4 kv = *(const float4*)(K + base);
                uint32_t hh, ll, h2, l2;
                split2(kv.x, kv.y, hh, ll); split2(kv.z, kv.w, h2, l2);
                *(uint2*)(smem + AKHI + r * STRA + c4 * 2) = make_uint2(hh, h2);
                *(uint2*)(smem + AKLO + r * STRA + c4 * 2) = make_uint2(ll, l2);
                float4 vv = *(const float4*)(V + base);
                split2(vv.x, vv.y, hh, ll); split2(vv.z, vv.w, h2, l2);
                *(uint2*)(smem + AVHI + r * STRA + c4 * 2) = make_uint2(hh, h2);
                *(uint2*)(smem + AVLO + r * STRA + c4 * 2) = make_uint2(ll, l2);
            }
            if (tid < 64) {
                int bi = b * SEQ + kt * 64 + tid;
                int mv = (mode == 0) ? (((const unsigned int*)mask)[bi] != 0u)
                                     : (((const unsigned char*)mask)[bi] != 0);
                ((float*)(smem + AMSK))[tid] = mv ? 1.f : 0.f;
            }
        }
        __syncthreads();

        float S[8][4];
        #pragma unroll
        for (int i = 0; i < 8; i++)
            #pragma unroll
            for (int j = 0; j < 4; j++) S[i][j] = 0.f;

        #pragma unroll
        for (int kf = 0; kf < 4; kf++) {
            uint32_t Bh[4][4], Bl[4][4];
            #pragma unroll
            for (int nf16 = 0; nf16 < 4; nf16++) {
                uint32_t bo = sb + (uint32_t)((nf16 * 16 + browB) * STRA + kf * 32) + bcolB;
                ldmx4(Bh[nf16], bo + AKHI);
                ldmx4(Bl[nf16], bo + AKLO);
            }
            #pragma unroll
            for (int nf16 = 0; nf16 < 4; nf16++) {
                #pragma unroll
                for (int hf = 0; hf < 2; hf++) {
                    float* sp = S[nf16 * 2 + hf];
                    uint32_t bh0 = Bh[nf16][hf * 2], bh1 = Bh[nf16][hf * 2 + 1];
                    uint32_t bl0 = Bl[nf16][hf * 2], bl1 = Bl[nf16][hf * 2 + 1];
                    mma16816(sp, Aqh[kf], bh0, bh1);
                    mma16816(sp, Aqh[kf], bl0, bl1);
                    mma16816(sp, Aql[kf], bh0, bh1);
                }
            }
        }

        const float* mk = (const float*)(smem + AMSK);
        float tmax_r = -1e30f, tmax_r2 = -1e30f;
        #pragma unroll
        for (int nf = 0; nf < 8; nf++) {
            int col = nf * 8 + (lane & 3) * 2;
            float m0v = mk[col], m1v = mk[col + 1];
            S[nf][0] = (m0v != 0.f) ? -1e9f : S[nf][0] * 0.125f;
            S[nf][1] = (m1v != 0.f) ? -1e9f : S[nf][1] * 0.125f;
            S[nf][2] = (m0v != 0.f) ? -1e9f : S[nf][2] * 0.125f;
            S[nf][3] = (m1v != 0.f) ? -1e9f : S[nf][3] * 0.125f;
            tmax_r  = fmaxf(tmax_r,  fmaxf(S[nf][0], S[nf][1]));
            tmax_r2 = fmaxf(tmax_r2, fmaxf(S[nf][2], S[nf][3]));
        }
        #pragma unroll
        for (int d = 1; d <= 2; d <<= 1) {
            tmax_r  = fmaxf(tmax_r,  __shfl_xor_sync(0xffffffffu, tmax_r,  d));
            tmax_r2 = fmaxf(tmax_r2, __shfl_xor_sync(0xffffffffu, tmax_r2, d));
        }

        float mnew_r  = fmaxf(m_r,  tmax_r);
        float mnew_r2 = fmaxf(m_r2, tmax_r2);
        float corr_r  = __expf(m_r  - mnew_r);
        float corr_r2 = __expf(m_r2 - mnew_r2);
        l_r *= corr_r; l_r2 *= corr_r2;
        #pragma unroll
        for (int nf = 0; nf < 8; nf++) {
            Oa[nf][0] *= corr_r;  Oa[nf][1] *= corr_r;
            Oa[nf][2] *= corr_r2; Oa[nf][3] *= corr_r2;
        }
        m_r = mnew_r; m_r2 = mnew_r2;

        uint32_t Ph[4][4], Pl[4][4];
        #pragma unroll
        for (int kf = 0; kf < 4; kf++) {
            float p00 = __expf(S[2*kf][0]   - mnew_r);
            float p01 = __expf(S[2*kf][1]   - mnew_r);
            float p02 = __expf(S[2*kf][2]   - mnew_r2);
            float p03 = __expf(S[2*kf][3]   - mnew_r2);
            float p10 = __expf(S[2*kf+1][0] - mnew_r);
            float p11 = __expf(S[2*kf+1][1] - mnew_r);
            float p12 = __expf(S[2*kf+1][2] - mnew_r2);
            float p13 = __expf(S[2*kf+1][3] - mnew_r2);
            l_r  += p00 + p01 + p10 + p11;
            l_r2 += p02 + p03 + p12 + p13;
            split2(p00, p01, Ph[kf][0], Pl[kf][0]);
            split2(p02, p03, Ph[kf][1], Pl[kf][1]);
            split2(p10, p11, Ph[kf][2], Pl[kf][2]);
            split2(p12, p13, Ph[kf][3], Pl[kf][3]);
        }

        #pragma unroll
        for (int kf = 0; kf < 4; kf++) {
            uint32_t Vh[4][4], Vl[4][4];
            #pragma unroll
            for (int df = 0; df < 4; df++) {
                uint32_t vo = sb + (uint32_t)((kf * 16 + vrowB) * STRA + df * 32) + vcolB;
                ldmx4t(Vh[df], vo + AVHI);
                ldmx4t(Vl[df], vo + AVLO);
            }
            #pragma unroll
            for (int df = 0; df < 4; df++) {
                #pragma unroll
                for (int hf = 0; hf < 2; hf++) {
                    float* op = Oa[df * 2 + hf];
                    uint32_t bh0 = Vh[df][hf * 2], bh1 = Vh[df][hf * 2 + 1];
                    uint32_t bl0 = Vl[df][hf * 2], bl1 = Vl[df][hf * 2 + 1];
                    mma16816(op, Ph[kf], bh0, bh1);
                    mma16816(op, Ph[kf], bl0, bl1);
                    mma16816(op, Pl[kf], bh0, bh1);
                }
            }
        }
    }

    #pragma unroll
    for (int d = 1; d <= 2; d <<= 1) {
        l_r  += __shfl_xor_sync(0xffffffffu, l_r,  d);
        l_r2 += __shfl_xor_sync(0xffffffffu, l_r2, d);
    }
    float inv_r = 1.f / l_r, inv_r2 = 1.f / l_r2;

    const int qa = b * SEQ + q0 + 16 * wid + (lane >> 2);
    const int qb2 = qa + 8;
    #pragma unroll
    for (int nf = 0; nf < 8; nf++) {
        int col = h * DK + nf * 8 + (lane & 3) * 2;
        *(float2*)(O + (size_t)qa  * D_MODEL + col) = make_float2(Oa[nf][0] * inv_r,  Oa[nf][1] * inv_r);
        *(float2*)(O + (size_t)qb2 * D_MODEL + col) = make_float2(Oa[nf][2] * inv_r2, Oa[nf][3] * inv_r2);
    }
}

// ---------------- residual + LayerNorm (torch: ddof=1, /(std+eps)) ----------------
__global__ __launch_bounds__(256)
void ln_kernel(const float* __restrict__ X, const float* __restrict__ R,
               const float* __restrict__ gamma, const float* __restrict__ beta,
               float* __restrict__ Y)
{
    const int row = blockIdx.x;
    const int tid = threadIdx.x;
    __shared__ float red1[8], red2[8];

    float v[3];
    float s = 0.f, ss = 0.f;
    #pragma unroll
    for (int i = 0; i < 3; i++) {
        int c = i * 256 + tid;
        float a = X[(size_t)row * D_MODEL + c] + R[(size_t)row * D_MODEL + c];
        v[i] = a; s += a; ss += a * a;
    }
    #pragma unroll
    for (int off = 16; off > 0; off >>= 1) {
        s  += __shfl_xor_sync(0xffffffffu, s,  off);
        ss += __shfl_xor_sync(0xffffffffu, ss, off);
    }
    const int wid = tid >> 5, lid = tid & 31;
    if (lid == 0) { red1[wid] = s; red2[wid] = ss; }
    __syncthreads();
    float ts = 0.f, tss = 0.f;
    #pragma unroll
    for (int i = 0; i < 8; i++) { ts += red1[i]; tss += red2[i]; }

    float mean = ts * (1.f / 768.f);
    float var  = (tss - 768.f * mean * mean) * (1.f / 767.f);
    var = fmaxf(var, 0.f);
    float denom = 1.f / (sqrtf(var) + LN_EPS);

    #pragma unroll
    for (int i = 0; i < 3; i++) {
        int c = i * 256 + tid;
        Y[(size_t)row * D_MODEL + c] = gamma[c] * (v[i] - mean) * denom + beta[c];
    }
}

// ---------------- launcher ----------------
extern "C" void kernel_launch(void* const* d_in, const int* in_sizes, int n_in,
                              void* d_out, int out_size)
{
    const float* x   = (const float*)d_in[0];
    const void*  mask=               d_in[1];
    const float* wq  = (const float*)d_in[2];
    const float* bq  = (const float*)d_in[3];
    const float* wk  = (const float*)d_in[4];
    const float* bk  = (const float*)d_in[5];
    const float* wv  = (const float*)d_in[6];
    const float* bv  = (const float*)d_in[7];
    const float* wo  = (const float*)d_in[8];
    const float* bo  = (const float*)d_in[9];
    const float* w1  = (const float*)d_in[10];
    const float* b1  = (const float*)d_in[11];
    const float* w2  = (const float*)d_in[12];
    const float* b2  = (const float*)d_in[13];
    const float* g1  = (const float*)d_in[14];
    const float* be1 = (const float*)d_in[15];
    const float* g2  = (const float*)d_in[16];
    const float* be2 = (const float*)d_in[17];
    float* out = (float*)d_out;

    static float *qb=nullptr,*kb=nullptr,*vb=nullptr,*attn=nullptr,*tmp=nullptr,*x1=nullptr,*ff1=nullptr;
    if (!qb) {
        cudaGetSymbolAddress((void**)&qb,   g_q);
        cudaGetSymbolAddress((void**)&kb,   g_k);
        cudaGetSymbolAddress((void**)&vb,   g_v);
        cudaGetSymbolAddress((void**)&attn, g_attn);
        cudaGetSymbolAddress((void**)&tmp,  g_tmp);
        cudaGetSymbolAddress((void**)&x1,   g_x1);
        cudaGetSymbolAddress((void**)&ff1,  g_ff1);
        cudaFuncSetAttribute(attention_mma, cudaFuncAttributeMaxDynamicSharedMemorySize, ATT_SMEM);
    }

    detect_mask_kernel<<<1, 1>>>((const unsigned int*)mask);

    dim3 g768(D_MODEL / 128, MTOK / 128);            // (6, 32)
    gemm_mma<0><<<g768, 256>>>(x, wq, bq, qb, MTOK, D_MODEL, D_MODEL);
    gemm_mma<0><<<g768, 256>>>(x, wk, bk, kb, MTOK, D_MODEL, D_MODEL);
    gemm_mma<0><<<g768, 256>>>(x, wv, bv, vb, MTOK, D_MODEL, D_MODEL);

    attention_mma<<<dim3(SEQ / 64, HEADS, BATCH), 128, ATT_SMEM>>>(qb, kb, vb, mask, attn);

    gemm_mma<0><<<g768, 256>>>(attn, wo, bo, tmp, MTOK, D_MODEL, D_MODEL);
    ln_kernel<<<MTOK, 256>>>(x, tmp, g1, be1, x1);

    gemm_mma<1><<<dim3(DFF / 128, MTOK / 128), 256>>>(x1, w1, b1, ff1, MTOK, DFF, D_MODEL);
    gemm_mma<0><<<g768, 256>>>(ff1, w2, b2, tmp, MTOK, D_MODEL, DFF);
    ln_kernel<<<MTOK, 256>>>(x1, tmp, g2, be2, out);
}